// round 8
// baseline (speedup 1.0000x reference)
#include <cuda_runtime.h>
#include <math.h>

// ---------------------------------------------------------------------------
// Problem constants
// ---------------------------------------------------------------------------
#define LSEQ   8192
#define KNODES 4096
#define ESZ    32
#define DSZ    64
#define NBINS  33          // D/2+1 rFFT bins
#define PI2F   6.283185307179586f
#define NB     148         // one block per SM: co-residency unconditionally guaranteed
#define NT     512         // 16 warps/SM (512*124 regs <= 64K regfile)
#define KSPLIT 18          // sumexp tasks = 2 qtiles * 4 heads * 18 = 144 <= NB
#define NGS    5           // gsyncs per launch (epoch math relies on this)

typedef unsigned long long ull;

// ---------------------------------------------------------------------------
// Device scratch (no allocations allowed)
// ---------------------------------------------------------------------------
struct Tup { float2 sa, sb, sc, sba, scb, scba; };

__device__ __align__(16) Tup   g_spart[NBINS * 8];
__device__ __align__(16) int   g_present[KNODES];        // epoch-tagged presence
__device__ __align__(16) float g_hsn[12 * DSZ];          // normalized softmax(hash)
__device__ __align__(16) float g_sgn[12];                // tanh(sign)
__device__ __align__(16) float g_h1[KNODES * ESZ];
__device__ __align__(16) float g_h2[KNODES * ESZ];
__device__ __align__(16) float g_Qc[KNODES * 32];
__device__ __align__(16) float g_Kc[KNODES * 32];
__device__ __align__(16) float g_Vc[KNODES * 32];
__device__ int   g_knmax[4];
__device__ __align__(16) float g_L[KNODES * 4];
__device__ __align__(16) float g_ACCA[KNODES * 32];
__device__ __align__(16) float g_accum[ESZ];
__device__ int   g_cnt;
__device__ int   g_bar_cnt;     // grid barrier arrive counter (returns to 0 each barrier)
__device__ int   g_bar_gen;     // grid barrier generation (monotonic across replays)

// ---------------------------------------------------------------------------
// helpers
// ---------------------------------------------------------------------------
__device__ __forceinline__ float2 cadd(float2 a, float2 b) { return make_float2(a.x + b.x, a.y + b.y); }
__device__ __forceinline__ float2 cmul(float2 a, float2 b) {
    return make_float2(a.x * b.x - a.y * b.y, a.x * b.y + a.y * b.x);
}
__device__ __forceinline__ float2 cfma(float2 a, float2 b, float2 c) {
    c.x = fmaf(a.x, b.x, fmaf(-a.y, b.y, c.x));
    c.y = fmaf(a.x, b.y, fmaf(a.y, b.x, c.y));
    return c;
}
__device__ __forceinline__ Tup tmerge(Tup X, Tup Y) {   // X = earlier segment
    Tup R;
    R.scba = cadd(cadd(X.scba, Y.scba), cadd(cmul(X.sa, Y.scb), cmul(X.sba, Y.sc)));
    R.scb  = cadd(cadd(X.scb,  Y.scb),  cmul(X.sb, Y.sc));
    R.sba  = cadd(cadd(X.sba,  Y.sba),  cmul(X.sa, Y.sb));
    R.sa = cadd(X.sa, Y.sa); R.sb = cadd(X.sb, Y.sb); R.sc = cadd(X.sc, Y.sc);
    return R;
}
__device__ __forceinline__ ull pack2(float lo, float hi) {
    ull r; asm("mov.b64 %0, {%1, %2};" : "=l"(r) : "f"(lo), "f"(hi)); return r;
}
__device__ __forceinline__ void unpack2(ull v, float& lo, float& hi) {
    asm("mov.b64 {%0, %1}, %2;" : "=f"(lo), "=f"(hi) : "l"(v));
}
__device__ __forceinline__ ull fma2(ull a, ull b, ull c) {
    ull d; asm("fma.rn.f32x2 %0, %1, %2, %3;" : "=l"(d) : "l"(a), "l"(b), "l"(c)); return d;
}

// ---- grid-wide barrier (generation-based; all NB blocks participate) ----
__device__ __forceinline__ int ld_acq(int* p) {
    int v; asm volatile("ld.acquire.gpu.b32 %0, [%1];" : "=r"(v) : "l"(p) : "memory"); return v;
}
__device__ __forceinline__ void st_rel(int* p, int v) {
    asm volatile("st.release.gpu.b32 [%0], %1;" :: "l"(p), "r"(v) : "memory");
}
__device__ __forceinline__ void gsync() {
    __threadfence();                     // publish this thread's writes
    __syncthreads();
    if (threadIdx.x == 0) {
        int gen = ld_acq(&g_bar_gen);
        int t = atomicAdd(&g_bar_cnt, 1);
        if (t == NB - 1) {
            atomicExch(&g_bar_cnt, 0);   // all arrived; none touch cnt until gen bump
            st_rel(&g_bar_gen, gen + 1);
        } else {
            while (ld_acq(&g_bar_gen) == gen) { __nanosleep(32); }
        }
    }
    __syncthreads();
    __threadfence();                     // gpu-scope: post-barrier loads see fresh data
}

// ---------------------------------------------------------------------------
// phase-union shared memory (~30KB; 1 block/SM always fits)
// ---------------------------------------------------------------------------
struct SkS { float2 cA[2][4], cB[2][4], cC[2][4]; Tup tp[512]; };          // dual-task sketch
struct H1S { float wt[32][32]; float bs[32]; float xs[32][33]; };
struct H2S { float wt[32][32]; float bs[32]; float ag[32][33]; int nb[32][4]; float nrm[32]; };
struct XqS { float wt[32][96]; float bs[96]; float ag[32][33]; int nb[32][4]; float nrm[32];
             float qs[32][96]; int slot[32]; };
struct SeS { ull ks2[512]; ull vs2[512]; };
struct MfS { float m[32], gm[32], c1[16], comb[128], f1[128]; float2 sT3[NBINS]; float sw[16][32]; };
union Smem { SkS sk; H1S h1; H2S h2; XqS xq; SeS se; MfS mf; };

// ---------------------------------------------------------------------------
// THE megakernel (persistent, 148 blocks x 512 threads, 5 grid barriers)
// ---------------------------------------------------------------------------
__global__ void __launch_bounds__(NT) mega_kernel(
    const int* __restrict__ seq,
    const float* __restrict__ hash_logits, const float* __restrict__ sign_logits,
    const float* __restrict__ emb,
    const float* __restrict__ gc1w, const float* __restrict__ gc1b,
    const float* __restrict__ gc2w, const float* __restrict__ gc2b,
    const float* __restrict__ aiw,  const float* __restrict__ aib,
    const float* __restrict__ aow,  const float* __restrict__ aob,
    const float* __restrict__ cw1,  const float* __restrict__ cb1,
    const float* __restrict__ cw2,  const float* __restrict__ cb2,
    const float* __restrict__ fw1,  const float* __restrict__ fb1,
    const float* __restrict__ fw2,  const float* __restrict__ fb2,
    float* __restrict__ out)
{
    __shared__ Smem sm;
    int tid = threadIdx.x, bid = blockIdx.x;
    int gtid = bid * NT + tid;
    // epoch: g_bar_gen increases by exactly NGS per launch; +1 never collides
    // with any epoch stored by a previous launch or the initial zeros.
    int epoch = ld_acq(&g_bar_gen) + 1;

    // ===== Phase 1: zero scratch, scatter presence, softmax table, h1 =====
    for (int i = gtid; i < KNODES * 32; i += NB * NT) g_ACCA[i] = 0.f;
    for (int i = gtid; i < KNODES * 4;  i += NB * NT) g_L[i] = 0.f;
    if (gtid < ESZ) g_accum[gtid] = 0.f;
    if (gtid < 4)   g_knmax[gtid] = 0;
    if (gtid == 0)  g_cnt = 0;

    if (gtid < LSEQ - 5) {                              // presence scatter (epoch-tagged)
        int t = gtid;
        int id = ((((seq[t] * 4 + seq[t + 1]) * 4 + seq[t + 2]) * 4 + seq[t + 3]) * 4
                  + seq[t + 4]) * 4 + seq[t + 5];
        g_present[id] = epoch;
    }

    if (bid == 0 && tid < 384) {                        // softmax tables, 12 warps
        int w = tid >> 5, lane = tid & 31;              // warp w = row w
        const float* row = hash_logits + w * DSZ;
        float v0 = row[lane], v1 = row[lane + 32];
        float mx = fmaxf(v0, v1);
        #pragma unroll
        for (int o = 16; o; o >>= 1) mx = fmaxf(mx, __shfl_xor_sync(0xffffffffu, mx, o));
        float e0 = expf(v0 - mx), e1 = expf(v1 - mx);
        float s = e0 + e1;
        #pragma unroll
        for (int o = 16; o; o >>= 1) s += __shfl_xor_sync(0xffffffffu, s, o);
        float inv = 1.f / s;
        g_hsn[w * DSZ + lane]      = e0 * inv;
        g_hsn[w * DSZ + lane + 32] = e1 * inv;
        if (lane == 0) g_sgn[w] = tanhf(sign_logits[w]);
    }

    if (bid < 128) {                                    // h1 tile: 32 nodes, 1024 outputs
        int base = bid * 32;
        for (int idx = tid; idx < 1024; idx += NT) {
            int e = idx >> 5, j = idx & 31;
            sm.h1.wt[j][e] = gc1w[idx];
        }
        if (tid < ESZ) sm.h1.bs[tid] = gc1b[tid];
        for (int idx = tid; idx < 1024; idx += NT)
            sm.h1.xs[idx >> 5][idx & 31] = emb[base * 32 + idx];
        __syncthreads();
        #pragma unroll
        for (int it = 0; it < 2; it++) {
            int idx = tid + it * NT;
            int n = idx >> 5, e = idx & 31;
            float acc = sm.h1.bs[e];
            #pragma unroll
            for (int j = 0; j < ESZ; j++) acc = fmaf(sm.h1.xs[n][j], sm.h1.wt[j][e], acc);
            g_h1[base * 32 + idx] = fmaxf(acc, 0.f);
        }
    }
    gsync();

    // ===== Phase 2: tensor-sketch, 264 tasks = 132 blocks x 2 sub-blocks =====
    if (bid < 132) {
        int sub = tid >> 8, stid = tid & 255;
        int task = bid * 2 + sub;                       // 0..263
        int bin = task % NBINS, seg = task / NBINS;
        if (stid < 192) {                               // DFT: 12 rows x 16 lanes x 4 terms
            int row = stid >> 4, l16 = stid & 15;
            float re = 0.f, im = 0.f;
            #pragma unroll
            for (int t = 0; t < 4; t++) {
                int d = l16 * 4 + t;
                float ang = -PI2F * (float)(bin * d) / (float)DSZ;
                float sn, cs; sincosf(ang, &sn, &cs);
                float hv = g_hsn[row * DSZ + d];
                re = fmaf(hv, cs, re);
                im = fmaf(hv, sn, im);
            }
            #pragma unroll
            for (int o = 8; o; o >>= 1) {
                re += __shfl_down_sync(0xffffffffu, re, o, 16);
                im += __shfl_down_sync(0xffffffffu, im, o, 16);
            }
            if (l16 == 0) {
                float f = g_sgn[row] * (1.f / (float)LSEQ);
                float2 v = make_float2(re * f, im * f);
                int p = row >> 2, c = row & 3;
                if (p == 0) sm.sk.cA[sub][c] = v;
                else if (p == 1) sm.sk.cB[sub][c] = v;
                else sm.sk.cC[sub][c] = v;
            }
        }
        __syncthreads();
        float2 sa = {0,0}, sb = {0,0}, sc = {0,0}, sba = {0,0}, scb = {0,0}, scba = {0,0};
        int t0 = seg * 1024 + stid * 4;
        #pragma unroll
        for (int i = 0; i < 4; i++) {
            int ch = seq[t0 + i];
            float2 a = sm.sk.cA[sub][ch], b = sm.sk.cB[sub][ch], c = sm.sk.cC[sub][ch];
            scba = cfma(c, sba, scba);
            scb  = cfma(c, sb,  scb);
            sba  = cfma(b, sa,  sba);
            sa = cadd(sa, a); sb = cadd(sb, b); sc = cadd(sc, c);
        }
        Tup me; me.sa = sa; me.sb = sb; me.sc = sc; me.sba = sba; me.scb = scb; me.scba = scba;
        sm.sk.tp[tid] = me;
        __syncthreads();
        for (int s = 128; s > 0; s >>= 1) {             // both subs: identical sync structure
            if (stid < s) sm.sk.tp[sub * 256 + stid] =
                tmerge(sm.sk.tp[sub * 256 + stid], sm.sk.tp[sub * 256 + stid + s]);
            __syncthreads();
        }
        if (stid == 0) g_spart[bin * 8 + seg] = sm.sk.tp[sub * 256];
    }
    gsync();

    // ===== Phase 3: h2 = relu((nadj@h1) @ gc2_w^T + b) =====
    if (bid < 128) {
        int base = bid * 32;
        for (int idx = tid; idx < 1024; idx += NT) {
            int e = idx >> 5, j = idx & 31;
            sm.h2.wt[j][e] = gc2w[idx];
        }
        if (tid < ESZ) sm.h2.bs[tid] = gc2b[tid];
        if (tid < 32) {
            int i = base + tid;
            bool pres = g_present[i] == epoch;
            int bse = (i & 1023) * 4;
            float cnt = 0.f;
            #pragma unroll
            for (int r = 0; r < 4; r++) {
                int j = bse + r;
                bool ok = pres && (j != i) && (g_present[j] == epoch);
                sm.h2.nb[tid][r] = ok ? j : -1;
                cnt += ok ? 1.f : 0.f;
            }
            sm.h2.nrm[tid] = pres ? 1.f / (cnt + 1e-6f) : 0.f;
        }
        __syncthreads();
        #pragma unroll
        for (int it = 0; it < 2; it++) {
            int idx = tid + it * NT;
            int n = idx >> 5, e = idx & 31;
            float a = 0.f;
            #pragma unroll
            for (int r = 0; r < 4; r++) {
                int j = sm.h2.nb[n][r];
                if (j >= 0) a += g_h1[j * 32 + e];
            }
            sm.h2.ag[n][e] = a * sm.h2.nrm[n];
        }
        __syncthreads();
        #pragma unroll
        for (int it = 0; it < 2; it++) {
            int idx = tid + it * NT;
            int n = idx >> 5, e = idx & 31;
            float acc = sm.h2.bs[e];
            #pragma unroll
            for (int j = 0; j < ESZ; j++) acc = fmaf(sm.h2.ag[n][j], sm.h2.wt[j][e], acc);
            g_h2[base * 32 + idx] = fmaxf(acc, 0.f);
        }
    }
    gsync();

    // ===== Phase 4: xqkv + fused compact (qkv never touches global) =====
    if (bid < 128) {
        int base = bid * 32;
        for (int idx = tid; idx < 96 * ESZ; idx += NT) {
            int o = idx >> 5, j = idx & 31;
            sm.xq.wt[j][o] = aiw[idx];
        }
        if (tid < 96) sm.xq.bs[tid] = aib[tid];
        if (tid < 32) {
            int i = base + tid;
            bool pres = g_present[i] == epoch;
            int bse = (i & 1023) * 4;
            float cnt = 0.f;
            #pragma unroll
            for (int r = 0; r < 4; r++) {
                int j = bse + r;
                bool ok = pres && (j != i) && (g_present[j] == epoch);
                sm.xq.nb[tid][r] = ok ? j : -1;
                cnt += ok ? 1.f : 0.f;
            }
            sm.xq.nrm[tid] = pres ? 1.f / (cnt + 1e-6f) : 0.f;
        }
        __syncthreads();
        #pragma unroll
        for (int it = 0; it < 2; it++) {
            int idx = tid + it * NT;
            int n = idx >> 5, e = idx & 31;
            float a = 0.f;
            #pragma unroll
            for (int r = 0; r < 4; r++) {
                int j = sm.xq.nb[n][r];
                if (j >= 0) a += g_h2[j * 32 + e];
            }
            sm.xq.ag[n][e] = a * sm.xq.nrm[n];
        }
        __syncthreads();
        #pragma unroll
        for (int it = 0; it < 6; it++) {
            int idx = tid + it * NT;                // idx = n*96 + o
            int n = idx / 96, o = idx - n * 96;
            float acc = sm.xq.bs[o];
            #pragma unroll
            for (int j = 0; j < ESZ; j++) acc = fmaf(sm.xq.ag[n][j], sm.xq.wt[j][o], acc);
            sm.xq.qs[n][o] = acc;
        }
        __syncthreads();
        if (tid < 32) {
            int i = base + tid;
            sm.xq.slot[tid] = (g_present[i] == epoch) ? atomicAdd(&g_cnt, 1) : -1;
        }
        __syncthreads();
        for (int idx = tid; idx < 3072; idx += NT) {
            int n = idx / 96, o = idx - n * 96;
            int p = sm.xq.slot[n];
            if (p >= 0) {
                float v = sm.xq.qs[n][o];
                if (o < 32)      g_Qc[p * 32 + o]        = v * 0.35355339059327373f;
                else if (o < 64) g_Kc[p * 32 + (o - 32)] = v;
                else             g_Vc[p * 32 + (o - 64)] = v;
            }
        }
        if (tid < 128) {
            int n = tid >> 2, h = tid & 3;
            if (sm.xq.slot[n] >= 0) {
                float ksq = 0.f;
                #pragma unroll
                for (int d = 0; d < 8; d++) {
                    float v = sm.xq.qs[n][32 + h * 8 + d];
                    ksq = fmaf(v, v, ksq);
                }
                atomicMax(&g_knmax[h], __float_as_int(ksq));  // ksq >= 0: bit-compare ok
            }
        }
    }
    gsync();

    // ===== Phase 5: single-pass softmax sums (upper-bound shift, f32x2) =====
    if (bid < 2 * 4 * KSPLIT) {              // 144 tasks: 2 qtiles x 4 heads x 18 ksplits
        int qt = bid & 1, h = (bid >> 1) & 3, z = bid >> 3;
        int np = g_cnt;
        float knorm = sqrtf(__int_as_float(g_knmax[h]));
        int qb = qt * 2048 + tid * 4;

        ull qp[4][4], c0[4], acc[4][4];
        float l[4];
        bool val[4];
        #pragma unroll
        for (int u = 0; u < 4; u++) {
            int qi = qb + u;
            val[u] = qi < np;
            float qv[8];
            #pragma unroll
            for (int d = 0; d < 8; d++) qv[d] = 0.f;
            if (val[u]) {
                float4 x0 = *(const float4*)&g_Qc[qi * 32 + h * 8];
                float4 x1 = *(const float4*)&g_Qc[qi * 32 + h * 8 + 4];
                qv[0]=x0.x; qv[1]=x0.y; qv[2]=x0.z; qv[3]=x0.w;
                qv[4]=x1.x; qv[5]=x1.y; qv[6]=x1.z; qv[7]=x1.w;
            }
            float qsq = 0.f;
            #pragma unroll
            for (int d = 0; d < 8; d++) qsq = fmaf(qv[d], qv[d], qsq);
            float mh = fminf(sqrtf(qsq) * knorm, 80.f);
            #pragma unroll
            for (int p = 0; p < 4; p++) qp[u][p] = pack2(qv[2*p], qv[2*p+1]);
            c0[u] = pack2(-mh, 0.f);
            l[u] = 0.f;
            #pragma unroll
            for (int p = 0; p < 4; p++) acc[u][p] = pack2(0.f, 0.f);
        }

        int kper = (np + KSPLIT - 1) / KSPLIT;
        int kbeg = z * kper, kend = min(np, kbeg + kper);
        for (int kt = kbeg; kt < kend; kt += 128) {
            int jn = min(128, kend - kt);
            __syncthreads();
            {
                int j = tid >> 2, p = tid & 3;      // 512 threads cover 128 keys x 4 pairs
                if (j < jn) {
                    sm.se.ks2[tid] = *(const ull*)&g_Kc[(kt + j) * 32 + h * 8 + p * 2];
                    sm.se.vs2[tid] = *(const ull*)&g_Vc[(kt + j) * 32 + h * 8 + p * 2];
                }
            }
            __syncthreads();
            #pragma unroll 2
            for (int j = 0; j < jn; j++) {
                ull k0 = sm.se.ks2[j*4], k1 = sm.se.ks2[j*4+1], k2 = sm.se.ks2[j*4+2], k3 = sm.se.ks2[j*4+3];
                ull v0 = sm.se.vs2[j*4], v1 = sm.se.vs2[j*4+1], v2 = sm.se.vs2[j*4+2], v3 = sm.se.vs2[j*4+3];
                #pragma unroll
                for (int u = 0; u < 4; u++) {
                    ull sp = fma2(qp[u][0], k0,
                             fma2(qp[u][1], k1,
                             fma2(qp[u][2], k2,
                             fma2(qp[u][3], k3, c0[u]))));
                    float lo, hi; unpack2(sp, lo, hi);
                    float w = __expf(lo + hi);        // = exp(s - m_hat)
                    l[u] += w;
                    ull wp = pack2(w, w);
                    acc[u][0] = fma2(wp, v0, acc[u][0]);
                    acc[u][1] = fma2(wp, v1, acc[u][1]);
                    acc[u][2] = fma2(wp, v2, acc[u][2]);
                    acc[u][3] = fma2(wp, v3, acc[u][3]);
                }
            }
        }

        #pragma unroll
        for (int u = 0; u < 4; u++) if (val[u]) {
            int qi = qb + u;
            atomicAdd(&g_L[qi * 4 + h], l[u]);
            #pragma unroll
            for (int p = 0; p < 4; p++) {
                float lo, hi; unpack2(acc[u][p], lo, hi);
                atomicAdd(&g_ACCA[(qi * 4 + h) * 8 + p * 2],     lo);
                atomicAdd(&g_ACCA[(qi * 4 + h) * 8 + p * 2 + 1], hi);
            }
        }
    }
    gsync();

    // ===== Phase 6: mean over present queries of ACC/L -> g_accum =====
    {
        int np = g_cnt;
        float vec[32];
        #pragma unroll
        for (int d = 0; d < 32; d++) vec[d] = 0.f;
        int q = gtid;                         // NB*NT = 75776 >= np: one q per thread
        if (q < np) {
            float4 lv = *(const float4*)&g_L[q * 4];
            float invh[4] = {1.f / lv.x, 1.f / lv.y, 1.f / lv.z, 1.f / lv.w};
            #pragma unroll
            for (int h = 0; h < 4; h++) {
                float4 a0 = *(const float4*)&g_ACCA[(q * 4 + h) * 8];
                float4 a1 = *(const float4*)&g_ACCA[(q * 4 + h) * 8 + 4];
                vec[h*8+0] = a0.x * invh[h]; vec[h*8+1] = a0.y * invh[h];
                vec[h*8+2] = a0.z * invh[h]; vec[h*8+3] = a0.w * invh[h];
                vec[h*8+4] = a1.x * invh[h]; vec[h*8+5] = a1.y * invh[h];
                vec[h*8+6] = a1.z * invh[h]; vec[h*8+7] = a1.w * invh[h];
            }
        }
        int lane = tid & 31, w = tid >> 5;
        #pragma unroll
        for (int d = 0; d < 32; d++) {
            float r = vec[d];
            for (int o = 16; o; o >>= 1) r += __shfl_xor_sync(0xffffffffu, r, o);
            if (lane == 0) sm.mf.sw[w][d] = r;
        }
        __syncthreads();
        if (tid < 32) {
            float s = 0.f;
            #pragma unroll
            for (int ww = 0; ww < 16; ww++) s += sm.mf.sw[ww][tid];
            if (s != 0.f) atomicAdd(&g_accum[tid], s);
        }
    }
    gsync();

    // ===== Phase 7 (block 0): sketch merge + out-proj + ctx + irfft + fusion =====
    if (bid == 0) {
        if (tid < NBINS) {                  // ordered merge of 8 sketch segments
            Tup acc = g_spart[tid * 8];
            #pragma unroll
            for (int s = 1; s < 8; s++) acc = tmerge(acc, g_spart[tid * 8 + s]);
            sm.mf.sT3[tid] = acc.scba;
        }
        float invNp = 1.f / (float)g_cnt;
        if (tid < 32) sm.mf.m[tid] = g_accum[tid] * invNp;
        __syncthreads();
        if (tid < 32) {
            float a = aob[tid];
            for (int j = 0; j < 32; j++) a = fmaf(sm.mf.m[j], aow[tid * 32 + j], a);
            sm.mf.gm[tid] = a;
        }
        __syncthreads();
        if (tid < 16) {
            float a = cb1[tid];
            for (int j = 0; j < 32; j++) a = fmaf(sm.mf.gm[j], cw1[tid * 32 + j], a);
            sm.mf.c1[tid] = fmaxf(a, 0.f);
        }
        __syncthreads();
        if (tid < 64) {
            float a = cb2[tid];
            for (int j = 0; j < 16; j++) a = fmaf(sm.mf.c1[j], cw2[tid * 16 + j], a);
            sm.mf.comb[64 + tid] = a;
            float2 T0 = sm.mf.sT3[0], T32 = sm.mf.sT3[32];
            float x = T0.x + ((tid & 1) ? -T32.x : T32.x);
            for (int k = 1; k < 32; k++) {
                float2 Tk = sm.mf.sT3[k];
                float ang = PI2F * (float)(k * tid) / (float)DSZ;
                float sn, cs; sincosf(ang, &sn, &cs);
                x += 2.f * (Tk.x * cs - Tk.y * sn);
            }
            sm.mf.comb[tid] = x * (1.f / (float)DSZ);
        }
        __syncthreads();
        if (tid < 128) {
            float a = fb1[tid];
            for (int j = 0; j < 128; j++) a = fmaf(sm.mf.comb[j], fw1[tid * 128 + j], a);
            sm.mf.f1[tid] = fmaxf(a, 0.f);
        }
        __syncthreads();
        if (tid < 64) {
            float a = fb2[tid];
            for (int j = 0; j < 128; j++) a = fmaf(sm.mf.f1[j], fw2[tid * 128 + j], a);
            out[tid] = tanhf(a);
        }
    }
}

// ---------------------------------------------------------------------------
// launch: ONE persistent kernel, 148 blocks x 512 threads
// ---------------------------------------------------------------------------
extern "C" void kernel_launch(void* const* d_in, const int* in_sizes, int n_in,
                              void* d_out, int out_size) {
    const int*   seq         = (const int*)  d_in[0];
    const float* hash_logits = (const float*)d_in[1];
    const float* sign_logits = (const float*)d_in[2];
    const float* kmer_emb    = (const float*)d_in[3];
    const float* gc1_w       = (const float*)d_in[4];
    const float* gc1_b       = (const float*)d_in[5];
    const float* gc2_w       = (const float*)d_in[6];
    const float* gc2_b       = (const float*)d_in[7];
    const float* attn_in_w   = (const float*)d_in[8];
    const float* attn_in_b   = (const float*)d_in[9];
    const float* attn_out_w  = (const float*)d_in[10];
    const float* attn_out_b  = (const float*)d_in[11];
    const float* ctx_w1      = (const float*)d_in[12];
    const float* ctx_b1      = (const float*)d_in[13];
    const float* ctx_w2      = (const float*)d_in[14];
    const float* ctx_b2      = (const float*)d_in[15];
    const float* fus_w1      = (const float*)d_in[16];
    const float* fus_b1      = (const float*)d_in[17];
    const float* fus_w2      = (const float*)d_in[18];
    const float* fus_b2      = (const float*)d_in[19];
    float* out = (float*)d_out;

    mega_kernel<<<NB, NT>>>(seq, hash_logits, sign_logits, kmer_emb,
                            gc1_w, gc1_b, gc2_w, gc2_b,
                            attn_in_w, attn_in_b, attn_out_w, attn_out_b,
                            ctx_w1, ctx_b1, ctx_w2, ctx_b2,
                            fus_w1, fus_b1, fus_w2, fus_b2, out);
}

// round 9
// speedup vs baseline: 1.1528x; 1.1528x over previous
#include <cuda_runtime.h>
#include <math.h>

// ---------------------------------------------------------------------------
// Problem constants
// ---------------------------------------------------------------------------
#define LSEQ   8192
#define KNODES 4096
#define ESZ    32
#define DSZ    64
#define NBINS  33          // D/2+1 rFFT bins
#define PI2F   6.283185307179586f
#define NB     148         // one block per SM: co-residency unconditionally guaranteed
#define NT     512         // 16 warps/SM
#define KSPLIT 9           // sumexp tasks = 4 qtiles * 4 heads * 9 = 144 <= NB

typedef unsigned long long ull;

// ---------------------------------------------------------------------------
// Device scratch (no allocations allowed)
// ---------------------------------------------------------------------------
struct Tup { float2 sa, sb, sc, sba, scb, scba; };

__device__ __align__(16) Tup   g_spart[NBINS * 8];
__device__ __align__(16) int   g_present[KNODES];        // epoch-tagged presence
__device__ __align__(16) float g_h1[KNODES * ESZ];
__device__ __align__(16) float g_h2[KNODES * ESZ];
__device__ __align__(16) float g_Qc[KNODES * 32];
__device__ __align__(16) float g_Kc[KNODES * 32];
__device__ __align__(16) float g_Vc[KNODES * 32];
__device__ int   g_knmax[4];
__device__ __align__(16) float g_L[KNODES * 4];
__device__ __align__(16) float g_ACCA[KNODES * 32];
__device__ __align__(16) float g_accum[ESZ];
__device__ int   g_cnt;
__device__ int   g_bar_cnt;     // grid barrier arrive counter (returns to 0 each barrier)
__device__ int   g_bar_gen;     // grid barrier generation (monotonic across replays)

// ---------------------------------------------------------------------------
// helpers
// ---------------------------------------------------------------------------
__device__ __forceinline__ float2 cadd(float2 a, float2 b) { return make_float2(a.x + b.x, a.y + b.y); }
__device__ __forceinline__ float2 cmul(float2 a, float2 b) {
    return make_float2(a.x * b.x - a.y * b.y, a.x * b.y + a.y * b.x);
}
__device__ __forceinline__ float2 cfma(float2 a, float2 b, float2 c) {
    c.x = fmaf(a.x, b.x, fmaf(-a.y, b.y, c.x));
    c.y = fmaf(a.x, b.y, fmaf(a.y, b.x, c.y));
    return c;
}
__device__ __forceinline__ Tup tmerge(Tup X, Tup Y) {   // X = earlier segment
    Tup R;
    R.scba = cadd(cadd(X.scba, Y.scba), cadd(cmul(X.sa, Y.scb), cmul(X.sba, Y.sc)));
    R.scb  = cadd(cadd(X.scb,  Y.scb),  cmul(X.sb, Y.sc));
    R.sba  = cadd(cadd(X.sba,  Y.sba),  cmul(X.sa, Y.sb));
    R.sa = cadd(X.sa, Y.sa); R.sb = cadd(X.sb, Y.sb); R.sc = cadd(X.sc, Y.sc);
    return R;
}
__device__ __forceinline__ ull pack2(float lo, float hi) {
    ull r; asm("mov.b64 %0, {%1, %2};" : "=l"(r) : "f"(lo), "f"(hi)); return r;
}
__device__ __forceinline__ void unpack2(ull v, float& lo, float& hi) {
    asm("mov.b64 {%0, %1}, %2;" : "=f"(lo), "=f"(hi) : "l"(v));
}
__device__ __forceinline__ ull fma2(ull a, ull b, ull c) {
    ull d; asm("fma.rn.f32x2 %0, %1, %2, %3;" : "=l"(d) : "l"(a), "l"(b), "l"(c)); return d;
}

// ---- grid-wide barrier: ONE gpu-scope fence per BLOCK (not per thread) ----
// Release/acquire protocol: bar.sync gives the intra-block hb edge; tid0's
// fence.acq_rel.gpu is cumulative over it, so the relaxed arrive publishes
// all block writes. Consumers synchronize via ld.acquire spin.
__device__ __forceinline__ int ld_acq(int* p) {
    int v; asm volatile("ld.acquire.gpu.b32 %0, [%1];" : "=r"(v) : "l"(p) : "memory"); return v;
}
__device__ __forceinline__ void st_rel(int* p, int v) {
    asm volatile("st.release.gpu.b32 [%0], %1;" :: "l"(p), "r"(v) : "memory");
}
__device__ __forceinline__ void gsync() {
    __syncthreads();
    if (threadIdx.x == 0) {
        asm volatile("fence.acq_rel.gpu;" ::: "memory");
        int gen = ld_acq(&g_bar_gen);
        int t = atomicAdd(&g_bar_cnt, 1);
        if (t == NB - 1) {
            g_bar_cnt = 0;                     // ordered before gen bump by st.release
            st_rel(&g_bar_gen, gen + 1);
        } else {
            while (ld_acq(&g_bar_gen) == gen) { __nanosleep(32); }
        }
    }
    __syncthreads();
}

// ---------------------------------------------------------------------------
// phase-union shared memory (~30KB; 1 block/SM always fits)
// ---------------------------------------------------------------------------
struct SkS { float hs[12][DSZ]; float sgs[12];
             float2 cA[2][4], cB[2][4], cC[2][4]; Tup tp[512]; };
struct H1S { float wt[32][32]; float bs[32]; float xs[32][33]; };
struct H2S { float wt[32][32]; float bs[32]; float ag[32][33]; int nb[32][4]; float nrm[32]; };
struct XqS { float wt[32][96]; float bs[96]; float ag[32][33]; int nb[32][4]; float nrm[32];
             float qs[32][96]; int slot[32]; };
struct SeS { ull ks2[512]; ull vs2[512]; };
struct MfS { float m[32], gm[32], c1[16], comb[128], f1[128]; float2 sT3[NBINS]; float sw[16][32]; };
union Smem { SkS sk; H1S h1; H2S h2; XqS xq; SeS se; MfS mf; };

// ---------------------------------------------------------------------------
// THE megakernel (persistent, 148 blocks x 512 threads, 5 grid barriers)
// ---------------------------------------------------------------------------
__global__ void __launch_bounds__(NT) mega_kernel(
    const int* __restrict__ seq,
    const float* __restrict__ hash_logits, const float* __restrict__ sign_logits,
    const float* __restrict__ emb,
    const float* __restrict__ gc1w, const float* __restrict__ gc1b,
    const float* __restrict__ gc2w, const float* __restrict__ gc2b,
    const float* __restrict__ aiw,  const float* __restrict__ aib,
    const float* __restrict__ aow,  const float* __restrict__ aob,
    const float* __restrict__ cw1,  const float* __restrict__ cb1,
    const float* __restrict__ cw2,  const float* __restrict__ cb2,
    const float* __restrict__ fw1,  const float* __restrict__ fb1,
    const float* __restrict__ fw2,  const float* __restrict__ fb2,
    float* __restrict__ out)
{
    __shared__ Smem sm;
    int tid = threadIdx.x, bid = blockIdx.x;
    int gtid = bid * NT + tid;
    // epoch: g_bar_gen increases by exactly 5 per launch; +1 never collides
    // with any epoch stored by a previous launch or the initial zeros.
    int epoch = ld_acq(&g_bar_gen) + 1;

    // ===== Phase 1: zero scratch, scatter, sketch (table in-block), h1 =====
    for (int i = gtid; i < KNODES * 32; i += NB * NT) g_ACCA[i] = 0.f;
    for (int i = gtid; i < KNODES * 4;  i += NB * NT) g_L[i] = 0.f;
    if (gtid < ESZ) g_accum[gtid] = 0.f;
    if (gtid < 4)   g_knmax[gtid] = 0;
    if (gtid == 0)  g_cnt = 0;

    if (gtid < LSEQ - 5) {                              // presence scatter (epoch-tagged)
        int t = gtid;
        int id = ((((seq[t] * 4 + seq[t + 1]) * 4 + seq[t + 2]) * 4 + seq[t + 3]) * 4
                  + seq[t + 4]) * 4 + seq[t + 5];
        g_present[id] = epoch;
    }

    if (bid < 132) {                                    // sketch: 2 tasks per block
        if (tid < 384) {                                // softmax tables: 12 warps, lane-||
            int w = tid >> 5, lane = tid & 31;
            const float* row = hash_logits + w * DSZ;
            float v0 = row[lane], v1 = row[lane + 32];
            float mx = fmaxf(v0, v1);
            #pragma unroll
            for (int o = 16; o; o >>= 1) mx = fmaxf(mx, __shfl_xor_sync(0xffffffffu, mx, o));
            float e0 = expf(v0 - mx), e1 = expf(v1 - mx);
            float s = e0 + e1;
            #pragma unroll
            for (int o = 16; o; o >>= 1) s += __shfl_xor_sync(0xffffffffu, s, o);
            float inv = 1.f / s;
            sm.sk.hs[w][lane]      = e0 * inv;
            sm.sk.hs[w][lane + 32] = e1 * inv;
            if (lane == 0) sm.sk.sgs[w] = tanhf(sign_logits[w]);
        }
        __syncthreads();
        int sub = tid >> 8, stid = tid & 255;
        int task = bid * 2 + sub;                       // 0..263
        int bin = task % NBINS, seg = task / NBINS;
        if (stid < 192) {                               // DFT: 12 rows x 16 lanes x 4 terms
            int row = stid >> 4, l16 = stid & 15;
            float re = 0.f, im = 0.f;
            #pragma unroll
            for (int t = 0; t < 4; t++) {
                int d = l16 * 4 + t;
                float ang = -PI2F * (float)(bin * d) / (float)DSZ;
                float sn, cs; sincosf(ang, &sn, &cs);
                float hv = sm.sk.hs[row][d];
                re = fmaf(hv, cs, re);
                im = fmaf(hv, sn, im);
            }
            #pragma unroll
            for (int o = 8; o; o >>= 1) {
                re += __shfl_down_sync(0xffffffffu, re, o, 16);
                im += __shfl_down_sync(0xffffffffu, im, o, 16);
            }
            if (l16 == 0) {
                float f = sm.sk.sgs[row] * (1.f / (float)LSEQ);
                float2 v = make_float2(re * f, im * f);
                int p = row >> 2, c = row & 3;
                if (p == 0) sm.sk.cA[sub][c] = v;
                else if (p == 1) sm.sk.cB[sub][c] = v;
                else sm.sk.cC[sub][c] = v;
            }
        }
        __syncthreads();
        float2 sa = {0,0}, sb = {0,0}, sc = {0,0}, sba = {0,0}, scb = {0,0}, scba = {0,0};
        int t0 = seg * 1024 + stid * 4;
        #pragma unroll
        for (int i = 0; i < 4; i++) {
            int ch = seq[t0 + i];
            float2 a = sm.sk.cA[sub][ch], b = sm.sk.cB[sub][ch], c = sm.sk.cC[sub][ch];
            scba = cfma(c, sba, scba);
            scb  = cfma(c, sb,  scb);
            sba  = cfma(b, sa,  sba);
            sa = cadd(sa, a); sb = cadd(sb, b); sc = cadd(sc, c);
        }
        Tup me; me.sa = sa; me.sb = sb; me.sc = sc; me.sba = sba; me.scb = scb; me.scba = scba;
        sm.sk.tp[tid] = me;
        __syncthreads();
        for (int s = 128; s > 0; s >>= 1) {             // both subs: identical sync structure
            if (stid < s) sm.sk.tp[sub * 256 + stid] =
                tmerge(sm.sk.tp[sub * 256 + stid], sm.sk.tp[sub * 256 + stid + s]);
            __syncthreads();
        }
        if (stid == 0) g_spart[bin * 8 + seg] = sm.sk.tp[sub * 256];
    }
    if (bid < 128) {                                    // h1 tile (after sketch; union reuse)
        int base = bid * 32;
        __syncthreads();
        for (int idx = tid; idx < 1024; idx += NT) {
            int e = idx >> 5, j = idx & 31;
            sm.h1.wt[j][e] = gc1w[idx];
        }
        if (tid < ESZ) sm.h1.bs[tid] = gc1b[tid];
        for (int idx = tid; idx < 1024; idx += NT)
            sm.h1.xs[idx >> 5][idx & 31] = emb[base * 32 + idx];
        __syncthreads();
        #pragma unroll
        for (int it = 0; it < 2; it++) {
            int idx = tid + it * NT;
            int n = idx >> 5, e = idx & 31;
            float acc = sm.h1.bs[e];
            #pragma unroll
            for (int j = 0; j < ESZ; j++) acc = fmaf(sm.h1.xs[n][j], sm.h1.wt[j][e], acc);
            g_h1[base * 32 + idx] = fmaxf(acc, 0.f);
        }
    }
    gsync();

    // ===== Phase 2: h2 = relu((nadj@h1) @ gc2_w^T + b) =====
    if (bid < 128) {
        int base = bid * 32;
        for (int idx = tid; idx < 1024; idx += NT) {
            int e = idx >> 5, j = idx & 31;
            sm.h2.wt[j][e] = gc2w[idx];
        }
        if (tid < ESZ) sm.h2.bs[tid] = gc2b[tid];
        if (tid < 32) {
            int i = base + tid;
            bool pres = g_present[i] == epoch;
            int bse = (i & 1023) * 4;
            float cnt = 0.f;
            #pragma unroll
            for (int r = 0; r < 4; r++) {
                int j = bse + r;
                bool ok = pres && (j != i) && (g_present[j] == epoch);
                sm.h2.nb[tid][r] = ok ? j : -1;
                cnt += ok ? 1.f : 0.f;
            }
            sm.h2.nrm[tid] = pres ? 1.f / (cnt + 1e-6f) : 0.f;
        }
        __syncthreads();
        #pragma unroll
        for (int it = 0; it < 2; it++) {
            int idx = tid + it * NT;
            int n = idx >> 5, e = idx & 31;
            float a = 0.f;
            #pragma unroll
            for (int r = 0; r < 4; r++) {
                int j = sm.h2.nb[n][r];
                if (j >= 0) a += g_h1[j * 32 + e];
            }
            sm.h2.ag[n][e] = a * sm.h2.nrm[n];
        }
        __syncthreads();
        #pragma unroll
        for (int it = 0; it < 2; it++) {
            int idx = tid + it * NT;
            int n = idx >> 5, e = idx & 31;
            float acc = sm.h2.bs[e];
            #pragma unroll
            for (int j = 0; j < ESZ; j++) acc = fmaf(sm.h2.ag[n][j], sm.h2.wt[j][e], acc);
            g_h2[base * 32 + idx] = fmaxf(acc, 0.f);
        }
    }
    gsync();

    // ===== Phase 3: xqkv + fused compact (qkv never touches global) =====
    if (bid < 128) {
        int base = bid * 32;
        for (int idx = tid; idx < 96 * ESZ; idx += NT) {
            int o = idx >> 5, j = idx & 31;
            sm.xq.wt[j][o] = aiw[idx];
        }
        if (tid < 96) sm.xq.bs[tid] = aib[tid];
        if (tid < 32) {
            int i = base + tid;
            bool pres = g_present[i] == epoch;
            int bse = (i & 1023) * 4;
            float cnt = 0.f;
            #pragma unroll
            for (int r = 0; r < 4; r++) {
                int j = bse + r;
                bool ok = pres && (j != i) && (g_present[j] == epoch);
                sm.xq.nb[tid][r] = ok ? j : -1;
                cnt += ok ? 1.f : 0.f;
            }
            sm.xq.nrm[tid] = pres ? 1.f / (cnt + 1e-6f) : 0.f;
        }
        __syncthreads();
        #pragma unroll
        for (int it = 0; it < 2; it++) {
            int idx = tid + it * NT;
            int n = idx >> 5, e = idx & 31;
            float a = 0.f;
            #pragma unroll
            for (int r = 0; r < 4; r++) {
                int j = sm.xq.nb[n][r];
                if (j >= 0) a += g_h2[j * 32 + e];
            }
            sm.xq.ag[n][e] = a * sm.xq.nrm[n];
        }
        __syncthreads();
        #pragma unroll
        for (int it = 0; it < 6; it++) {
            int idx = tid + it * NT;                // idx = n*96 + o
            int n = idx / 96, o = idx - n * 96;
            float acc = sm.xq.bs[o];
            #pragma unroll
            for (int j = 0; j < ESZ; j++) acc = fmaf(sm.xq.ag[n][j], sm.xq.wt[j][o], acc);
            sm.xq.qs[n][o] = acc;
        }
        __syncthreads();
        if (tid < 32) {
            int i = base + tid;
            sm.xq.slot[tid] = (g_present[i] == epoch) ? atomicAdd(&g_cnt, 1) : -1;
        }
        __syncthreads();
        for (int idx = tid; idx < 3072; idx += NT) {
            int n = idx / 96, o = idx - n * 96;
            int p = sm.xq.slot[n];
            if (p >= 0) {
                float v = sm.xq.qs[n][o];
                if (o < 32)      g_Qc[p * 32 + o]        = v * 0.35355339059327373f;
                else if (o < 64) g_Kc[p * 32 + (o - 32)] = v;
                else             g_Vc[p * 32 + (o - 64)] = v;
            }
        }
        if (tid < 128) {
            int n = tid >> 2, h = tid & 3;
            if (sm.xq.slot[n] >= 0) {
                float ksq = 0.f;
                #pragma unroll
                for (int d = 0; d < 8; d++) {
                    float v = sm.xq.qs[n][32 + h * 8 + d];
                    ksq = fmaf(v, v, ksq);
                }
                atomicMax(&g_knmax[h], __float_as_int(ksq));  // ksq >= 0: bit-compare ok
            }
        }
    }
    gsync();

    // ===== Phase 4: single-pass softmax sums (upper-bound shift, f32x2) =====
    if (bid < 4 * 4 * KSPLIT) {              // 144 tasks: 4 qtiles x 4 heads x 9 ksplits
        int qt = bid & 3, h = (bid >> 2) & 3, z = bid >> 4;
        int np = g_cnt;
        float knorm = sqrtf(__int_as_float(g_knmax[h]));
        int qb = qt * 1024 + tid * 2;

        ull qp[2][4], c0[2], acc[2][4];
        float l[2];
        bool val[2];
        #pragma unroll
        for (int u = 0; u < 2; u++) {
            int qi = qb + u;
            val[u] = qi < np;
            float qv[8];
            #pragma unroll
            for (int d = 0; d < 8; d++) qv[d] = 0.f;
            if (val[u]) {
                float4 x0 = *(const float4*)&g_Qc[qi * 32 + h * 8];
                float4 x1 = *(const float4*)&g_Qc[qi * 32 + h * 8 + 4];
                qv[0]=x0.x; qv[1]=x0.y; qv[2]=x0.z; qv[3]=x0.w;
                qv[4]=x1.x; qv[5]=x1.y; qv[6]=x1.z; qv[7]=x1.w;
            }
            float qsq = 0.f;
            #pragma unroll
            for (int d = 0; d < 8; d++) qsq = fmaf(qv[d], qv[d], qsq);
            float mh = fminf(sqrtf(qsq) * knorm, 80.f);
            #pragma unroll
            for (int p = 0; p < 4; p++) qp[u][p] = pack2(qv[2*p], qv[2*p+1]);
            c0[u] = pack2(-mh, 0.f);
            l[u] = 0.f;
            #pragma unroll
            for (int p = 0; p < 4; p++) acc[u][p] = pack2(0.f, 0.f);
        }

        int kper = (np + KSPLIT - 1) / KSPLIT;
        int kbeg = z * kper, kend = min(np, kbeg + kper);
        for (int kt = kbeg; kt < kend; kt += 128) {
            int jn = min(128, kend - kt);
            __syncthreads();
            {
                int j = tid >> 2, p = tid & 3;      // 512 threads cover 128 keys x 4 pairs
                if (j < jn) {
                    sm.se.ks2[tid] = *(const ull*)&g_Kc[(kt + j) * 32 + h * 8 + p * 2];
                    sm.se.vs2[tid] = *(const ull*)&g_Vc[(kt + j) * 32 + h * 8 + p * 2];
                }
            }
            __syncthreads();
            #pragma unroll 4
            for (int j = 0; j < jn; j++) {
                ull k0 = sm.se.ks2[j*4], k1 = sm.se.ks2[j*4+1], k2 = sm.se.ks2[j*4+2], k3 = sm.se.ks2[j*4+3];
                ull v0 = sm.se.vs2[j*4], v1 = sm.se.vs2[j*4+1], v2 = sm.se.vs2[j*4+2], v3 = sm.se.vs2[j*4+3];
                #pragma unroll
                for (int u = 0; u < 2; u++) {
                    ull sp = fma2(qp[u][0], k0,
                             fma2(qp[u][1], k1,
                             fma2(qp[u][2], k2,
                             fma2(qp[u][3], k3, c0[u]))));
                    float lo, hi; unpack2(sp, lo, hi);
                    float w = __expf(lo + hi);        // = exp(s - m_hat)
                    l[u] += w;
                    ull wp = pack2(w, w);
                    acc[u][0] = fma2(wp, v0, acc[u][0]);
                    acc[u][1] = fma2(wp, v1, acc[u][1]);
                    acc[u][2] = fma2(wp, v2, acc[u][2]);
                    acc[u][3] = fma2(wp, v3, acc[u][3]);
                }
            }
        }

        #pragma unroll
        for (int u = 0; u < 2; u++) if (val[u]) {
            int qi = qb + u;
            atomicAdd(&g_L[qi * 4 + h], l[u]);
            #pragma unroll
            for (int p = 0; p < 4; p++) {
                float lo, hi; unpack2(acc[u][p], lo, hi);
                atomicAdd(&g_ACCA[(qi * 4 + h) * 8 + p * 2],     lo);
                atomicAdd(&g_ACCA[(qi * 4 + h) * 8 + p * 2 + 1], hi);
            }
        }
    }
    gsync();

    // ===== Phase 5: mean over present queries of ACC/L -> g_accum =====
    {
        int np = g_cnt;
        float vec[32];
        #pragma unroll
        for (int d = 0; d < 32; d++) vec[d] = 0.f;
        int q = gtid;                         // NB*NT = 75776 >= np: one q per thread
        if (q < np) {
            float4 lv = *(const float4*)&g_L[q * 4];
            float invh[4] = {1.f / lv.x, 1.f / lv.y, 1.f / lv.z, 1.f / lv.w};
            #pragma unroll
            for (int h = 0; h < 4; h++) {
                float4 a0 = *(const float4*)&g_ACCA[(q * 4 + h) * 8];
                float4 a1 = *(const float4*)&g_ACCA[(q * 4 + h) * 8 + 4];
                vec[h*8+0] = a0.x * invh[h]; vec[h*8+1] = a0.y * invh[h];
                vec[h*8+2] = a0.z * invh[h]; vec[h*8+3] = a0.w * invh[h];
                vec[h*8+4] = a1.x * invh[h]; vec[h*8+5] = a1.y * invh[h];
                vec[h*8+6] = a1.z * invh[h]; vec[h*8+7] = a1.w * invh[h];
            }
        }
        int lane = tid & 31, w = tid >> 5;
        #pragma unroll
        for (int d = 0; d < 32; d++) {
            float r = vec[d];
            for (int o = 16; o; o >>= 1) r += __shfl_xor_sync(0xffffffffu, r, o);
            if (lane == 0) sm.mf.sw[w][d] = r;
        }
        __syncthreads();
        if (tid < 32) {
            float s = 0.f;
            #pragma unroll
            for (int ww = 0; ww < 16; ww++) s += sm.mf.sw[ww][tid];
            if (s != 0.f) atomicAdd(&g_accum[tid], s);
        }
    }
    gsync();

    // ===== Phase 6 (block 0): sketch merge + out-proj + ctx + irfft + fusion =====
    if (bid == 0) {
        if (tid < NBINS) {                  // ordered merge of 8 sketch segments
            Tup acc = g_spart[tid * 8];
            #pragma unroll
            for (int s = 1; s < 8; s++) acc = tmerge(acc, g_spart[tid * 8 + s]);
            sm.mf.sT3[tid] = acc.scba;
        }
        float invNp = 1.f / (float)g_cnt;
        if (tid < 32) sm.mf.m[tid] = g_accum[tid] * invNp;
        __syncthreads();
        if (tid < 32) {
            float a = aob[tid];
            for (int j = 0; j < 32; j++) a = fmaf(sm.mf.m[j], aow[tid * 32 + j], a);
            sm.mf.gm[tid] = a;
        }
        __syncthreads();
        if (tid < 16) {
            float a = cb1[tid];
            for (int j = 0; j < 32; j++) a = fmaf(sm.mf.gm[j], cw1[tid * 32 + j], a);
            sm.mf.c1[tid] = fmaxf(a, 0.f);
        }
        __syncthreads();
        if (tid < 64) {
            float a = cb2[tid];
            for (int j = 0; j < 16; j++) a = fmaf(sm.mf.c1[j], cw2[tid * 16 + j], a);
            sm.mf.comb[64 + tid] = a;
            float2 T0 = sm.mf.sT3[0], T32 = sm.mf.sT3[32];
            float x = T0.x + ((tid & 1) ? -T32.x : T32.x);
            for (int k = 1; k < 32; k++) {
                float2 Tk = sm.mf.sT3[k];
                float ang = PI2F * (float)(k * tid) / (float)DSZ;
                float sn, cs; sincosf(ang, &sn, &cs);
                x += 2.f * (Tk.x * cs - Tk.y * sn);
            }
            sm.mf.comb[tid] = x * (1.f / (float)DSZ);
        }
        __syncthreads();
        if (tid < 128) {
            float a = fb1[tid];
            for (int j = 0; j < 128; j++) a = fmaf(sm.mf.comb[j], fw1[tid * 128 + j], a);
            sm.mf.f1[tid] = fmaxf(a, 0.f);
        }
        __syncthreads();
        if (tid < 64) {
            float a = fb2[tid];
            for (int j = 0; j < 128; j++) a = fmaf(sm.mf.f1[j], fw2[tid * 128 + j], a);
            out[tid] = tanhf(a);
        }
    }
}

// ---------------------------------------------------------------------------
// launch: ONE persistent kernel, 148 blocks x 512 threads
// ---------------------------------------------------------------------------
extern "C" void kernel_launch(void* const* d_in, const int* in_sizes, int n_in,
                              void* d_out, int out_size) {
    const int*   seq         = (const int*)  d_in[0];
    const float* hash_logits = (const float*)d_in[1];
    const float* sign_logits = (const float*)d_in[2];
    const float* kmer_emb    = (const float*)d_in[3];
    const float* gc1_w       = (const float*)d_in[4];
    const float* gc1_b       = (const float*)d_in[5];
    const float* gc2_w       = (const float*)d_in[6];
    const float* gc2_b       = (const float*)d_in[7];
    const float* attn_in_w   = (const float*)d_in[8];
    const float* attn_in_b   = (const float*)d_in[9];
    const float* attn_out_w  = (const float*)d_in[10];
    const float* attn_out_b  = (const float*)d_in[11];
    const float* ctx_w1      = (const float*)d_in[12];
    const float* ctx_b1      = (const float*)d_in[13];
    const float* ctx_w2      = (const float*)d_in[14];
    const float* ctx_b2      = (const float*)d_in[15];
    const float* fus_w1      = (const float*)d_in[16];
    const float* fus_b1      = (const float*)d_in[17];
    const float* fus_w2      = (const float*)d_in[18];
    const float* fus_b2      = (const float*)d_in[19];
    float* out = (float*)d_out;

    mega_kernel<<<NB, NT>>>(seq, hash_logits, sign_logits, kmer_emb,
                            gc1_w, gc1_b, gc2_w, gc2_b,
                            attn_in_w, attn_in_b, attn_out_w, attn_out_b,
                            ctx_w1, ctx_b1, ctx_w2, ctx_b2,
                            fus_w1, fus_b1, fus_w2, fus_b2, out);
}